// round 12
// baseline (speedup 1.0000x reference)
#include <cuda_runtime.h>
#include <cuda_fp16.h>
#include <mma.h>
#include <cstdint>

using namespace nvcuda;

// Problem constants
#define HH 8
#define BB 2
#define NN 2048
#define FF 256
#define OO 64
#define BN (BB*NN)      // 4096
#define HBN (HH*BB*NN)  // 32768
#define CAP 256         // per-warp smem cache of neighbor (off, s_src)

// -------- scratch (static device globals; no runtime allocation) ----------
__device__ __half g_xh[(size_t)BN * FF];        // x in fp16, 2 MB
__device__ __half g_wh[(size_t)HH * FF * OO];   // W in fp16, 256 KB
__device__ __half g_hh[(size_t)HH * BN * OO];   // h [H,B*N,O] fp16, 4 MB
__device__ float  g_wa_src[HH * FF];            // W @ a_src  [H,F]
__device__ float  g_wa_dst[HH * FF];            // W @ a_dst  [H,F]
__device__ float  g_ssrc[HBN];                  // [H, B*N]
__device__ float  g_sdst[HBN];                  // [H, B*N]
__device__ int    g_nbr[(size_t)BN * NN];       // neighbor lists
__device__ int    g_cnt[BN];                    // per-row neighbor counts

// ------ K_wa: wa[h,f] = sum_o W[h,f,o]*a[h,o] (fp32 exact) + W->fp16 -------
// warp per (h,f) row of W.
__global__ void k_wa(const float* __restrict__ W,
                     const float* __restrict__ a_src, const float* __restrict__ a_dst) {
    int gw = (blockIdx.x * blockDim.x + threadIdx.x) >> 5;   // h*FF + f
    int lane = threadIdx.x & 31;
    if (gw >= HH * FF) return;
    int h = gw >> 8;
    const float2 wv = ((const float2*)(W + (size_t)gw * OO))[lane];

    // fused fp16 conversion of W
    ((__half2*)g_wh)[(size_t)gw * 32 + lane] = __floats2half2_rn(wv.x, wv.y);

    const float2 as2 = ((const float2*)(a_src + h * OO))[lane];
    const float2 ad2 = ((const float2*)(a_dst + h * OO))[lane];
    float s = wv.x * as2.x + wv.y * as2.y;
    float d = wv.x * ad2.x + wv.y * ad2.y;
    #pragma unroll
    for (int o = 16; o; o >>= 1) {
        s += __shfl_xor_sync(0xffffffffu, s, o);
        d += __shfl_xor_sync(0xffffffffu, d, o);
    }
    if (lane == 0) { g_wa_src[gw] = s; g_wa_dst[gw] = d; }
}

// ------ K_scores: s = x @ wa (fp32 exact) + x->fp16 ------------------------
// warp per bn-row, all 8 heads. wa staged in smem as float2.
__global__ void k_scores(const float* __restrict__ x) {
    __shared__ float2 ws2[HH * FF / 2];   // 8 KB
    __shared__ float2 wd2[HH * FF / 2];   // 8 KB
    int tid = threadIdx.x;
    #pragma unroll
    for (int i = 0; i < 4; i++) {
        ws2[tid + i * 256] = ((const float2*)g_wa_src)[tid + i * 256];
        wd2[tid + i * 256] = ((const float2*)g_wa_dst)[tid + i * 256];
    }
    __syncthreads();

    int row  = blockIdx.x * 8 + (tid >> 5);
    int lane = tid & 31;

    const float2* xr = (const float2*)(x + (size_t)row * FF);
    float2 xv[4];
    #pragma unroll
    for (int k = 0; k < 4; k++) xv[k] = xr[k * 32 + lane];

    // fused fp16 conversion of x (coalesced half2 stores)
    __half2* xh = (__half2*)(g_xh + (size_t)row * FF);
    #pragma unroll
    for (int k = 0; k < 4; k++) xh[k * 32 + lane] = __floats2half2_rn(xv[k].x, xv[k].y);

    #pragma unroll
    for (int h = 0; h < HH; h++) {
        float ps = 0.0f, pd = 0.0f;
        #pragma unroll
        for (int k = 0; k < 4; k++) {
            float2 a = ws2[h * (FF/2) + k * 32 + lane];
            float2 b = wd2[h * (FF/2) + k * 32 + lane];
            ps = fmaf(xv[k].x, a.x, fmaf(xv[k].y, a.y, ps));
            pd = fmaf(xv[k].x, b.x, fmaf(xv[k].y, b.y, pd));
        }
        #pragma unroll
        for (int o = 16; o; o >>= 1) {
            ps += __shfl_xor_sync(0xffffffffu, ps, o);
            pd += __shfl_xor_sync(0xffffffffu, pd, o);
        }
        if (lane == 0) {
            g_ssrc[h * BN + row] = ps;
            g_sdst[h * BN + row] = pd;
        }
    }
}

// ---------------- fp16 tensor-core GEMM: h = x @ W[h] ----------------------
// Block tile 64x64, 4 warps (2x2), warp tile 32x32, K step 16.
__global__ void k_hgemm(int dummy) {
    __shared__ __align__(16) char smbuf[16384];
    __half* sx = (__half*)smbuf;             // 64 x 16
    __half* sw = sx + 64 * 16;               // 16 x 64
    float*  so = (float*)smbuf;              // 64 x 64 (epilogue)

    const int h  = blockIdx.y;
    const int m0 = blockIdx.x * 64;
    const int tid = threadIdx.x;             // 128 threads
    const int wid = tid >> 5;
    const int wm = wid >> 1, wn = wid & 1;

    wmma::fragment<wmma::accumulator, 16, 16, 16, float> acc[2][2];
    #pragma unroll
    for (int i = 0; i < 2; i++)
        #pragma unroll
        for (int j = 0; j < 2; j++) wmma::fill_fragment(acc[i][j], 0.0f);

    const __half* xg = g_xh + (size_t)m0 * FF;
    const __half* wg = g_wh + (size_t)h * FF * OO;

    for (int k0 = 0; k0 < FF; k0 += 16) {
        {
            int r = tid >> 1, cb = (tid & 1) * 8;
            *(uint4*)(sx + r * 16 + cb) = *(const uint4*)(xg + (size_t)r * FF + k0 + cb);
        }
        {
            int r = tid >> 3, cb = (tid & 7) * 8;
            *(uint4*)(sw + r * 64 + cb) = *(const uint4*)(wg + (size_t)(k0 + r) * OO + cb);
        }
        __syncthreads();

        wmma::fragment<wmma::matrix_a, 16, 16, 16, __half, wmma::row_major> af[2];
        wmma::fragment<wmma::matrix_b, 16, 16, 16, __half, wmma::row_major> bf[2];
        #pragma unroll
        for (int i = 0; i < 2; i++)
            wmma::load_matrix_sync(af[i], sx + (wm * 32 + i * 16) * 16, 16);
        #pragma unroll
        for (int j = 0; j < 2; j++)
            wmma::load_matrix_sync(bf[j], sw + wn * 32 + j * 16, 64);
        #pragma unroll
        for (int i = 0; i < 2; i++)
            #pragma unroll
            for (int j = 0; j < 2; j++)
                wmma::mma_sync(acc[i][j], af[i], bf[j], acc[i][j]);
        __syncthreads();
    }

    #pragma unroll
    for (int i = 0; i < 2; i++)
        #pragma unroll
        for (int j = 0; j < 2; j++)
            wmma::store_matrix_sync(so + (wm * 32 + i * 16) * 64 + wn * 32 + j * 16,
                                    acc[i][j], 64, wmma::mem_row_major);
    __syncthreads();

    __half* hb = g_hh + ((size_t)h * BN + m0) * OO;
    {
        int r = tid >> 1, cb = (tid & 1) * 32;
        #pragma unroll
        for (int k = 0; k < 8; k++) {
            float4 v = *(float4*)(so + r * 64 + cb + k * 4);
            __half2 p0 = __floats2half2_rn(v.x, v.y);
            __half2 p1 = __floats2half2_rn(v.z, v.w);
            uint2 p; p.x = *(unsigned*)&p0; p.y = *(unsigned*)&p1;
            *(uint2*)(hb + (size_t)r * OO + cb + k * 4) = p;
        }
    }
}

// ---------------- K0: adjacency compaction (warp/row, float4 + scan) -------
__global__ void k_compact(const float* __restrict__ adj) {
    int warp = (blockIdx.x * blockDim.x + threadIdx.x) >> 5;
    int lane = threadIdx.x & 31;
    if (warp >= BN) return;
    const float4* row = (const float4*)(adj + (size_t)warp * NN);
    int* out = g_nbr + (size_t)warp * NN;
    int base = 0;
    #pragma unroll 4
    for (int it = 0; it < NN / 128; it++) {          // 16 iterations
        float4 v = row[it * 32 + lane];
        int c0 = v.x > 0.0f, c1 = v.y > 0.0f, c2 = v.z > 0.0f, c3 = v.w > 0.0f;
        int cnt = c0 + c1 + c2 + c3;
        int inc = cnt;
        #pragma unroll
        for (int o = 1; o < 32; o <<= 1) {
            int n = __shfl_up_sync(0xffffffffu, inc, o);
            if (lane >= o) inc += n;
        }
        int pos = base + inc - cnt;
        int j0 = (it * 32 + lane) * 4;
        if (c0) out[pos++] = j0;
        if (c1) out[pos++] = j0 + 1;
        if (c2) out[pos++] = j0 + 2;
        if (c3) out[pos++] = j0 + 3;
        base += __shfl_sync(0xffffffffu, inc, 31);
    }
    if (lane == 0) g_cnt[warp] = base;
}

__device__ __forceinline__ float lrelu(float x) { return x > 0.0f ? x : 0.2f * x; }

// ---------------- K3: fused masked softmax + aggregation -------------------
// Warp per (h,b,i). Pass 1 caches (uint4-offset, s_src[j]) per neighbor in
// smem (CAP entries; gmem fallback beyond). Pass 2: lane-parallel exp
// weights, 4 neighbors per LDG.128 iteration via lane-group broadcast.
__global__ void k_att(float* __restrict__ out) {
    __shared__ int   s_off[8][CAP];
    __shared__ float s_ssv[8][CAP];

    int gw = (blockIdx.x * blockDim.x + threadIdx.x) >> 5;
    int lane = threadIdx.x & 31;
    if (gw >= HBN) return;
    const int w = (threadIdx.x >> 5);

    const int h   = gw / BN;
    const int rem = gw - h * BN;          // b*N + i
    const int b   = rem / NN;

    const int    c   = g_cnt[rem];
    const int*   lst = g_nbr + (size_t)rem * NN;
    const float* ss  = g_ssrc + (size_t)h * BN + (size_t)b * NN;
    const float  sdi = g_sdst[gw];

    // pass 1: row max (lrelu monotone) + cache (off, ss) in smem
    float m = -1e30f;
    for (int t = lane; t < c; t += 32) {
        int j = lst[t];
        float sv = ss[j];
        m = fmaxf(m, sv);
        if (t < CAP) { s_off[w][t] = j * 8; s_ssv[w][t] = sv; }
    }
    #pragma unroll
    for (int o = 16; o; o >>= 1) m = fmaxf(m, __shfl_xor_sync(0xffffffffu, m, o));
    const float rowmax = lrelu(sdi + m);
    __syncwarp();

    // pass 2
    const uint4* base = (const uint4*)(g_hh + ((size_t)h * BN + (size_t)b * NN) * OO);
    const int g = lane >> 3;
    const int s = lane & 7;

    float2 a0 = {0,0}, a1 = {0,0}, a2 = {0,0}, a3 = {0,0};
    float Z = 0.0f;

    for (int t0 = 0; t0 < c; t0 += 32) {
        int   t = t0 + lane;
        float e = 0.0f;
        int   off = 0;
        if (t < c) {
            float sv;
            if (t < CAP) { off = s_off[w][t]; sv = s_ssv[w][t]; }
            else         { int j = lst[t]; off = j * 8; sv = ss[j]; }
            e = __expf(lrelu(sdi + sv) - rowmax);
        }
        Z += e;
        #pragma unroll
        for (int k = 0; k < 8; k++) {
            int   idx = k * 4 + g;
            float ek  = __shfl_sync(0xffffffffu, e,   idx);
            int   ofk = __shfl_sync(0xffffffffu, off, idx);
            uint4 raw = base[ofk + s];
            const __half2* ph = (const __half2*)&raw;
            float2 f0 = __half22float2(ph[0]);
            float2 f1 = __half22float2(ph[1]);
            float2 f2 = __half22float2(ph[2]);
            float2 f3 = __half22float2(ph[3]);
            a0.x = fmaf(ek, f0.x, a0.x); a0.y = fmaf(ek, f0.y, a0.y);
            a1.x = fmaf(ek, f1.x, a1.x); a1.y = fmaf(ek, f1.y, a1.y);
            a2.x = fmaf(ek, f2.x, a2.x); a2.y = fmaf(ek, f2.y, a2.y);
            a3.x = fmaf(ek, f3.x, a3.x); a3.y = fmaf(ek, f3.y, a3.y);
        }
    }

    // combine lane groups (xor 8, 16) and reduce Z (full butterfly)
    #pragma unroll
    for (int o = 8; o <= 16; o <<= 1) {
        a0.x += __shfl_xor_sync(0xffffffffu, a0.x, o);
        a0.y += __shfl_xor_sync(0xffffffffu, a0.y, o);
        a1.x += __shfl_xor_sync(0xffffffffu, a1.x, o);
        a1.y += __shfl_xor_sync(0xffffffffu, a1.y, o);
        a2.x += __shfl_xor_sync(0xffffffffu, a2.x, o);
        a2.y += __shfl_xor_sync(0xffffffffu, a2.y, o);
        a3.x += __shfl_xor_sync(0xffffffffu, a3.x, o);
        a3.y += __shfl_xor_sync(0xffffffffu, a3.y, o);
    }
    #pragma unroll
    for (int o = 16; o; o >>= 1) Z += __shfl_xor_sync(0xffffffffu, Z, o);

    if (lane < 8) {
        float inv = 1.0f / Z;
        float4 r0 = make_float4(fmaxf(a0.x*inv,0.f), fmaxf(a0.y*inv,0.f),
                                fmaxf(a1.x*inv,0.f), fmaxf(a1.y*inv,0.f));
        float4 r1 = make_float4(fmaxf(a2.x*inv,0.f), fmaxf(a2.y*inv,0.f),
                                fmaxf(a3.x*inv,0.f), fmaxf(a3.y*inv,0.f));
        float* op = out + (size_t)rem * (HH * OO) + h * OO + s * 8;
        ((float4*)op)[0] = r0;
        ((float4*)op)[1] = r1;
    }
}

// --------------------------------- launch ---------------------------------
extern "C" void kernel_launch(void* const* d_in, const int* in_sizes, int n_in,
                              void* d_out, int out_size) {
    const float* x     = (const float*)d_in[0];
    const float* adj   = (const float*)d_in[1];
    const float* W     = (const float*)d_in[2];
    const float* a_src = (const float*)d_in[3];
    const float* a_dst = (const float*)d_in[4];
    float* out = (float*)d_out;

    k_wa<<<(HH * FF * 32) / 256, 256>>>(W, a_src, a_dst);
    k_compact<<<(BN * 32) / 256, 256>>>(adj);
    k_scores<<<BN / 8, 256>>>(x);
    k_hgemm<<<dim3(BN / 64, HH), 128>>>(0);
    k_att<<<(HBN * 32) / 256, 256>>>(out);
}

// round 13
// speedup vs baseline: 1.0126x; 1.0126x over previous
#include <cuda_runtime.h>
#include <cuda_fp16.h>
#include <mma.h>
#include <cstdint>

using namespace nvcuda;

// Problem constants
#define HH 8
#define BB 2
#define NN 2048
#define FF 256
#define OO 64
#define BN (BB*NN)      // 4096
#define HBN (HH*BB*NN)  // 32768
#define CAP 256         // per-warp smem cache of neighbor (off, s_src)

// -------- scratch (static device globals; no runtime allocation) ----------
__device__ __half g_xh[(size_t)BN * FF];        // x in fp16, 2 MB
__device__ __half g_wh[(size_t)HH * FF * OO];   // W in fp16, 256 KB
__device__ __half g_hh[(size_t)HH * BN * OO];   // h [H,B*N,O] fp16, 4 MB
__device__ float  g_wa_src[HH * FF];            // W @ a_src  [H,F]
__device__ float  g_wa_dst[HH * FF];            // W @ a_dst  [H,F]
__device__ float  g_ssrc[HBN];                  // [H, B*N]
__device__ float  g_sdst[HBN];                  // [H, B*N]
__device__ int    g_nbr[(size_t)BN * NN];       // neighbor lists
__device__ int    g_cnt[BN];                    // per-row neighbor counts

// ------ K_wa: wa[h,f] = sum_o W[h,f,o]*a[h,o] (fp32 exact) + W->fp16 -------
// warp per (h,f) row of W.
__global__ void k_wa(const float* __restrict__ W,
                     const float* __restrict__ a_src, const float* __restrict__ a_dst) {
    int gw = (blockIdx.x * blockDim.x + threadIdx.x) >> 5;   // h*FF + f
    int lane = threadIdx.x & 31;
    if (gw >= HH * FF) return;
    int h = gw >> 8;
    const float2 wv = ((const float2*)(W + (size_t)gw * OO))[lane];

    // fused fp16 conversion of W
    ((__half2*)g_wh)[(size_t)gw * 32 + lane] = __floats2half2_rn(wv.x, wv.y);

    const float2 as2 = ((const float2*)(a_src + h * OO))[lane];
    const float2 ad2 = ((const float2*)(a_dst + h * OO))[lane];
    float s = wv.x * as2.x + wv.y * as2.y;
    float d = wv.x * ad2.x + wv.y * ad2.y;
    #pragma unroll
    for (int o = 16; o; o >>= 1) {
        s += __shfl_xor_sync(0xffffffffu, s, o);
        d += __shfl_xor_sync(0xffffffffu, d, o);
    }
    if (lane == 0) { g_wa_src[gw] = s; g_wa_dst[gw] = d; }
}

// ------ K_scores: s = x @ wa (fp32 exact) + x->fp16 ------------------------
// warp per bn-row, all 8 heads. wa staged in smem as float2.
__global__ void k_scores(const float* __restrict__ x) {
    __shared__ float2 ws2[HH * FF / 2];   // 8 KB
    __shared__ float2 wd2[HH * FF / 2];   // 8 KB
    int tid = threadIdx.x;
    #pragma unroll
    for (int i = 0; i < 4; i++) {
        ws2[tid + i * 256] = ((const float2*)g_wa_src)[tid + i * 256];
        wd2[tid + i * 256] = ((const float2*)g_wa_dst)[tid + i * 256];
    }
    __syncthreads();

    int row  = blockIdx.x * 8 + (tid >> 5);
    int lane = tid & 31;

    const float2* xr = (const float2*)(x + (size_t)row * FF);
    float2 xv[4];
    #pragma unroll
    for (int k = 0; k < 4; k++) xv[k] = xr[k * 32 + lane];

    // fused fp16 conversion of x (coalesced half2 stores)
    __half2* xh = (__half2*)(g_xh + (size_t)row * FF);
    #pragma unroll
    for (int k = 0; k < 4; k++) xh[k * 32 + lane] = __floats2half2_rn(xv[k].x, xv[k].y);

    #pragma unroll
    for (int h = 0; h < HH; h++) {
        float ps = 0.0f, pd = 0.0f;
        #pragma unroll
        for (int k = 0; k < 4; k++) {
            float2 a = ws2[h * (FF/2) + k * 32 + lane];
            float2 b = wd2[h * (FF/2) + k * 32 + lane];
            ps = fmaf(xv[k].x, a.x, fmaf(xv[k].y, a.y, ps));
            pd = fmaf(xv[k].x, b.x, fmaf(xv[k].y, b.y, pd));
        }
        #pragma unroll
        for (int o = 16; o; o >>= 1) {
            ps += __shfl_xor_sync(0xffffffffu, ps, o);
            pd += __shfl_xor_sync(0xffffffffu, pd, o);
        }
        if (lane == 0) {
            g_ssrc[h * BN + row] = ps;
            g_sdst[h * BN + row] = pd;
        }
    }
}

// ---------------- fp16 tensor-core GEMM: h = x @ W[h] ----------------------
// Block tile 64x64, 4 warps (2x2), warp tile 32x32, K step 16.
__global__ void k_hgemm(int dummy) {
    __shared__ __align__(16) char smbuf[16384];
    __half* sx = (__half*)smbuf;             // 64 x 16
    __half* sw = sx + 64 * 16;               // 16 x 64
    float*  so = (float*)smbuf;              // 64 x 64 (epilogue)

    const int h  = blockIdx.y;
    const int m0 = blockIdx.x * 64;
    const int tid = threadIdx.x;             // 128 threads
    const int wid = tid >> 5;
    const int wm = wid >> 1, wn = wid & 1;

    wmma::fragment<wmma::accumulator, 16, 16, 16, float> acc[2][2];
    #pragma unroll
    for (int i = 0; i < 2; i++)
        #pragma unroll
        for (int j = 0; j < 2; j++) wmma::fill_fragment(acc[i][j], 0.0f);

    const __half* xg = g_xh + (size_t)m0 * FF;
    const __half* wg = g_wh + (size_t)h * FF * OO;

    for (int k0 = 0; k0 < FF; k0 += 16) {
        {
            int r = tid >> 1, cb = (tid & 1) * 8;
            *(uint4*)(sx + r * 16 + cb) = *(const uint4*)(xg + (size_t)r * FF + k0 + cb);
        }
        {
            int r = tid >> 3, cb = (tid & 7) * 8;
            *(uint4*)(sw + r * 64 + cb) = *(const uint4*)(wg + (size_t)(k0 + r) * OO + cb);
        }
        __syncthreads();

        wmma::fragment<wmma::matrix_a, 16, 16, 16, __half, wmma::row_major> af[2];
        wmma::fragment<wmma::matrix_b, 16, 16, 16, __half, wmma::row_major> bf[2];
        #pragma unroll
        for (int i = 0; i < 2; i++)
            wmma::load_matrix_sync(af[i], sx + (wm * 32 + i * 16) * 16, 16);
        #pragma unroll
        for (int j = 0; j < 2; j++)
            wmma::load_matrix_sync(bf[j], sw + wn * 32 + j * 16, 64);
        #pragma unroll
        for (int i = 0; i < 2; i++)
            #pragma unroll
            for (int j = 0; j < 2; j++)
                wmma::mma_sync(acc[i][j], af[i], bf[j], acc[i][j]);
        __syncthreads();
    }

    #pragma unroll
    for (int i = 0; i < 2; i++)
        #pragma unroll
        for (int j = 0; j < 2; j++)
            wmma::store_matrix_sync(so + (wm * 32 + i * 16) * 64 + wn * 32 + j * 16,
                                    acc[i][j], 64, wmma::mem_row_major);
    __syncthreads();

    __half* hb = g_hh + ((size_t)h * BN + m0) * OO;
    {
        int r = tid >> 1, cb = (tid & 1) * 32;
        #pragma unroll
        for (int k = 0; k < 8; k++) {
            float4 v = *(float4*)(so + r * 64 + cb + k * 4);
            __half2 p0 = __floats2half2_rn(v.x, v.y);
            __half2 p1 = __floats2half2_rn(v.z, v.w);
            uint2 p; p.x = *(unsigned*)&p0; p.y = *(unsigned*)&p1;
            *(uint2*)(hb + (size_t)r * OO + cb + k * 4) = p;
        }
    }
}

// ---------------- K0: adjacency compaction (warp/row, float4 + scan) -------
__global__ void k_compact(const float* __restrict__ adj) {
    int warp = (blockIdx.x * blockDim.x + threadIdx.x) >> 5;
    int lane = threadIdx.x & 31;
    if (warp >= BN) return;
    const float4* row = (const float4*)(adj + (size_t)warp * NN);
    int* out = g_nbr + (size_t)warp * NN;
    int base = 0;
    #pragma unroll 4
    for (int it = 0; it < NN / 128; it++) {          // 16 iterations
        float4 v = row[it * 32 + lane];
        int c0 = v.x > 0.0f, c1 = v.y > 0.0f, c2 = v.z > 0.0f, c3 = v.w > 0.0f;
        int cnt = c0 + c1 + c2 + c3;
        int inc = cnt;
        #pragma unroll
        for (int o = 1; o < 32; o <<= 1) {
            int n = __shfl_up_sync(0xffffffffu, inc, o);
            if (lane >= o) inc += n;
        }
        int pos = base + inc - cnt;
        int j0 = (it * 32 + lane) * 4;
        if (c0) out[pos++] = j0;
        if (c1) out[pos++] = j0 + 1;
        if (c2) out[pos++] = j0 + 2;
        if (c3) out[pos++] = j0 + 3;
        base += __shfl_sync(0xffffffffu, inc, 31);
    }
    if (lane == 0) g_cnt[warp] = base;
}

__device__ __forceinline__ float lrelu(float x) { return x > 0.0f ? x : 0.2f * x; }

// ---------------- K3: fused masked softmax + aggregation -------------------
// Warp per (h,b,i). Pass 1 caches (uint4-offset, s_src[j]) per neighbor in
// smem (CAP entries; gmem fallback beyond). Pass 2: lane-parallel exp
// weights, 4 neighbors per LDG.128 iteration via lane-group broadcast.
__global__ void k_att(float* __restrict__ out) {
    __shared__ int   s_off[8][CAP];
    __shared__ float s_ssv[8][CAP];

    int gw = (blockIdx.x * blockDim.x + threadIdx.x) >> 5;
    int lane = threadIdx.x & 31;
    if (gw >= HBN) return;
    const int w = (threadIdx.x >> 5);

    const int h   = gw / BN;
    const int rem = gw - h * BN;          // b*N + i
    const int b   = rem / NN;

    const int    c   = g_cnt[rem];
    const int*   lst = g_nbr + (size_t)rem * NN;
    const float* ss  = g_ssrc + (size_t)h * BN + (size_t)b * NN;
    const float  sdi = g_sdst[gw];

    // pass 1: row max (lrelu monotone) + cache (off, ss) in smem
    float m = -1e30f;
    for (int t = lane; t < c; t += 32) {
        int j = lst[t];
        float sv = ss[j];
        m = fmaxf(m, sv);
        if (t < CAP) { s_off[w][t] = j * 8; s_ssv[w][t] = sv; }
    }
    #pragma unroll
    for (int o = 16; o; o >>= 1) m = fmaxf(m, __shfl_xor_sync(0xffffffffu, m, o));
    const float rowmax = lrelu(sdi + m);
    __syncwarp();

    // pass 2
    const uint4* base = (const uint4*)(g_hh + ((size_t)h * BN + (size_t)b * NN) * OO);
    const int g = lane >> 3;
    const int s = lane & 7;

    float2 a0 = {0,0}, a1 = {0,0}, a2 = {0,0}, a3 = {0,0};
    float Z = 0.0f;

    for (int t0 = 0; t0 < c; t0 += 32) {
        int   t = t0 + lane;
        float e = 0.0f;
        int   off = 0;
        if (t < c) {
            float sv;
            if (t < CAP) { off = s_off[w][t]; sv = s_ssv[w][t]; }
            else         { int j = lst[t]; off = j * 8; sv = ss[j]; }
            e = __expf(lrelu(sdi + sv) - rowmax);
        }
        Z += e;
        #pragma unroll
        for (int k = 0; k < 8; k++) {
            int   idx = k * 4 + g;
            float ek  = __shfl_sync(0xffffffffu, e,   idx);
            int   ofk = __shfl_sync(0xffffffffu, off, idx);
            uint4 raw = base[ofk + s];
            const __half2* ph = (const __half2*)&raw;
            float2 f0 = __half22float2(ph[0]);
            float2 f1 = __half22float2(ph[1]);
            float2 f2 = __half22float2(ph[2]);
            float2 f3 = __half22float2(ph[3]);
            a0.x = fmaf(ek, f0.x, a0.x); a0.y = fmaf(ek, f0.y, a0.y);
            a1.x = fmaf(ek, f1.x, a1.x); a1.y = fmaf(ek, f1.y, a1.y);
            a2.x = fmaf(ek, f2.x, a2.x); a2.y = fmaf(ek, f2.y, a2.y);
            a3.x = fmaf(ek, f3.x, a3.x); a3.y = fmaf(ek, f3.y, a3.y);
        }
    }

    // combine lane groups (xor 8, 16) and reduce Z (full butterfly)
    #pragma unroll
    for (int o = 8; o <= 16; o <<= 1) {
        a0.x += __shfl_xor_sync(0xffffffffu, a0.x, o);
        a0.y += __shfl_xor_sync(0xffffffffu, a0.y, o);
        a1.x += __shfl_xor_sync(0xffffffffu, a1.x, o);
        a1.y += __shfl_xor_sync(0xffffffffu, a1.y, o);
        a2.x += __shfl_xor_sync(0xffffffffu, a2.x, o);
        a2.y += __shfl_xor_sync(0xffffffffu, a2.y, o);
        a3.x += __shfl_xor_sync(0xffffffffu, a3.x, o);
        a3.y += __shfl_xor_sync(0xffffffffu, a3.y, o);
    }
    #pragma unroll
    for (int o = 16; o; o >>= 1) Z += __shfl_xor_sync(0xffffffffu, Z, o);

    if (lane < 8) {
        float inv = 1.0f / Z;
        float4 r0 = make_float4(fmaxf(a0.x*inv,0.f), fmaxf(a0.y*inv,0.f),
                                fmaxf(a1.x*inv,0.f), fmaxf(a1.y*inv,0.f));
        float4 r1 = make_float4(fmaxf(a2.x*inv,0.f), fmaxf(a2.y*inv,0.f),
                                fmaxf(a3.x*inv,0.f), fmaxf(a3.y*inv,0.f));
        float* op = out + (size_t)rem * (HH * OO) + h * OO + s * 8;
        ((float4*)op)[0] = r0;
        ((float4*)op)[1] = r1;
    }
}

// --------------------------------- launch ---------------------------------
extern "C" void kernel_launch(void* const* d_in, const int* in_sizes, int n_in,
                              void* d_out, int out_size) {
    const float* x     = (const float*)d_in[0];
    const float* adj   = (const float*)d_in[1];
    const float* W     = (const float*)d_in[2];
    const float* a_src = (const float*)d_in[3];
    const float* a_dst = (const float*)d_in[4];
    float* out = (float*)d_out;

    k_wa<<<(HH * FF * 32) / 256, 256>>>(W, a_src, a_dst);
    k_compact<<<(BN * 32) / 256, 256>>>(adj);
    k_scores<<<BN / 8, 256>>>(x);
    k_hgemm<<<dim3(BN / 64, HH), 128>>>(0);
    k_att<<<(HBN * 32) / 256, 256>>>(out);
}

// round 14
// speedup vs baseline: 1.0177x; 1.0051x over previous
#include <cuda_runtime.h>
#include <cuda_fp16.h>
#include <mma.h>
#include <cstdint>

using namespace nvcuda;

// Problem constants
#define HH 8
#define BB 2
#define NN 2048
#define FF 256
#define OO 64
#define BN (BB*NN)      // 4096
#define HBN (HH*BB*NN)  // 32768
#define CAP 256         // per-warp smem cache of neighbor (off, s_src)

// -------- scratch (static device globals; no runtime allocation) ----------
__device__ __half g_xh[(size_t)BN * FF];        // x in fp16, 2 MB
__device__ __half g_wh[(size_t)HH * FF * OO];   // W in fp16, 256 KB
__device__ __half g_hh[(size_t)HH * BN * OO];   // h [H,B*N,O] fp16, 4 MB
__device__ float  g_wa_src[HH * FF];            // W @ a_src  [H,F]
__device__ float  g_wa_dst[HH * FF];            // W @ a_dst  [H,F]
__device__ float  g_ssrc[HBN];                  // [H, B*N]
__device__ float  g_sdst[HBN];                  // [H, B*N]
__device__ int    g_nbr[(size_t)BN * NN];       // neighbor lists
__device__ int    g_cnt[BN];                    // per-row neighbor counts

// ------ K_wa: wa[h,f] = sum_o W[h,f,o]*a[h,o] (fp32 exact) + W->fp16 -------
// warp per (h,f) row of W.
__global__ void k_wa(const float* __restrict__ W,
                     const float* __restrict__ a_src, const float* __restrict__ a_dst) {
    int gw = (blockIdx.x * blockDim.x + threadIdx.x) >> 5;   // h*FF + f
    int lane = threadIdx.x & 31;
    if (gw >= HH * FF) return;
    int h = gw >> 8;
    const float2 wv = ((const float2*)(W + (size_t)gw * OO))[lane];

    // fused fp16 conversion of W
    ((__half2*)g_wh)[(size_t)gw * 32 + lane] = __floats2half2_rn(wv.x, wv.y);

    const float2 as2 = ((const float2*)(a_src + h * OO))[lane];
    const float2 ad2 = ((const float2*)(a_dst + h * OO))[lane];
    float s = wv.x * as2.x + wv.y * as2.y;
    float d = wv.x * ad2.x + wv.y * ad2.y;
    #pragma unroll
    for (int o = 16; o; o >>= 1) {
        s += __shfl_xor_sync(0xffffffffu, s, o);
        d += __shfl_xor_sync(0xffffffffu, d, o);
    }
    if (lane == 0) { g_wa_src[gw] = s; g_wa_dst[gw] = d; }
}

// ------ K_scores: s = x @ wa (fp32 exact) + x->fp16 ------------------------
// warp per bn-row, all 8 heads. wa staged in smem as float2.
__global__ void k_scores(const float* __restrict__ x) {
    __shared__ float2 ws2[HH * FF / 2];   // 8 KB
    __shared__ float2 wd2[HH * FF / 2];   // 8 KB
    int tid = threadIdx.x;
    #pragma unroll
    for (int i = 0; i < 4; i++) {
        ws2[tid + i * 256] = ((const float2*)g_wa_src)[tid + i * 256];
        wd2[tid + i * 256] = ((const float2*)g_wa_dst)[tid + i * 256];
    }
    __syncthreads();

    int row  = blockIdx.x * 8 + (tid >> 5);
    int lane = tid & 31;

    const float2* xr = (const float2*)(x + (size_t)row * FF);
    float2 xv[4];
    #pragma unroll
    for (int k = 0; k < 4; k++) xv[k] = xr[k * 32 + lane];

    // fused fp16 conversion of x (coalesced half2 stores)
    __half2* xh = (__half2*)(g_xh + (size_t)row * FF);
    #pragma unroll
    for (int k = 0; k < 4; k++) xh[k * 32 + lane] = __floats2half2_rn(xv[k].x, xv[k].y);

    #pragma unroll
    for (int h = 0; h < HH; h++) {
        float ps = 0.0f, pd = 0.0f;
        #pragma unroll
        for (int k = 0; k < 4; k++) {
            float2 a = ws2[h * (FF/2) + k * 32 + lane];
            float2 b = wd2[h * (FF/2) + k * 32 + lane];
            ps = fmaf(xv[k].x, a.x, fmaf(xv[k].y, a.y, ps));
            pd = fmaf(xv[k].x, b.x, fmaf(xv[k].y, b.y, pd));
        }
        #pragma unroll
        for (int o = 16; o; o >>= 1) {
            ps += __shfl_xor_sync(0xffffffffu, ps, o);
            pd += __shfl_xor_sync(0xffffffffu, pd, o);
        }
        if (lane == 0) {
            g_ssrc[h * BN + row] = ps;
            g_sdst[h * BN + row] = pd;
        }
    }
}

// ---------------- fp16 tensor-core GEMM: h = x @ W[h] ----------------------
// Block tile 64x64, 4 warps (2x2), warp tile 32x32, K step 16.
__global__ void k_hgemm(int dummy) {
    __shared__ __align__(16) char smbuf[16384];
    __half* sx = (__half*)smbuf;             // 64 x 16
    __half* sw = sx + 64 * 16;               // 16 x 64
    float*  so = (float*)smbuf;              // 64 x 64 (epilogue)

    const int h  = blockIdx.y;
    const int m0 = blockIdx.x * 64;
    const int tid = threadIdx.x;             // 128 threads
    const int wid = tid >> 5;
    const int wm = wid >> 1, wn = wid & 1;

    wmma::fragment<wmma::accumulator, 16, 16, 16, float> acc[2][2];
    #pragma unroll
    for (int i = 0; i < 2; i++)
        #pragma unroll
        for (int j = 0; j < 2; j++) wmma::fill_fragment(acc[i][j], 0.0f);

    const __half* xg = g_xh + (size_t)m0 * FF;
    const __half* wg = g_wh + (size_t)h * FF * OO;

    for (int k0 = 0; k0 < FF; k0 += 16) {
        {
            int r = tid >> 1, cb = (tid & 1) * 8;
            *(uint4*)(sx + r * 16 + cb) = *(const uint4*)(xg + (size_t)r * FF + k0 + cb);
        }
        {
            int r = tid >> 3, cb = (tid & 7) * 8;
            *(uint4*)(sw + r * 64 + cb) = *(const uint4*)(wg + (size_t)(k0 + r) * OO + cb);
        }
        __syncthreads();

        wmma::fragment<wmma::matrix_a, 16, 16, 16, __half, wmma::row_major> af[2];
        wmma::fragment<wmma::matrix_b, 16, 16, 16, __half, wmma::row_major> bf[2];
        #pragma unroll
        for (int i = 0; i < 2; i++)
            wmma::load_matrix_sync(af[i], sx + (wm * 32 + i * 16) * 16, 16);
        #pragma unroll
        for (int j = 0; j < 2; j++)
            wmma::load_matrix_sync(bf[j], sw + wn * 32 + j * 16, 64);
        #pragma unroll
        for (int i = 0; i < 2; i++)
            #pragma unroll
            for (int j = 0; j < 2; j++)
                wmma::mma_sync(acc[i][j], af[i], bf[j], acc[i][j]);
        __syncthreads();
    }

    #pragma unroll
    for (int i = 0; i < 2; i++)
        #pragma unroll
        for (int j = 0; j < 2; j++)
            wmma::store_matrix_sync(so + (wm * 32 + i * 16) * 64 + wn * 32 + j * 16,
                                    acc[i][j], 64, wmma::mem_row_major);
    __syncthreads();

    __half* hb = g_hh + ((size_t)h * BN + m0) * OO;
    {
        int r = tid >> 1, cb = (tid & 1) * 32;
        #pragma unroll
        for (int k = 0; k < 8; k++) {
            float4 v = *(float4*)(so + r * 64 + cb + k * 4);
            __half2 p0 = __floats2half2_rn(v.x, v.y);
            __half2 p1 = __floats2half2_rn(v.z, v.w);
            uint2 p; p.x = *(unsigned*)&p0; p.y = *(unsigned*)&p1;
            *(uint2*)(hb + (size_t)r * OO + cb + k * 4) = p;
        }
    }
}

// ---------------- K0: adjacency compaction (warp/row, float4 + scan) -------
__global__ void k_compact(const float* __restrict__ adj) {
    int warp = (blockIdx.x * blockDim.x + threadIdx.x) >> 5;
    int lane = threadIdx.x & 31;
    if (warp >= BN) return;
    const float4* row = (const float4*)(adj + (size_t)warp * NN);
    int* out = g_nbr + (size_t)warp * NN;
    int base = 0;
    #pragma unroll 4
    for (int it = 0; it < NN / 128; it++) {          // 16 iterations
        float4 v = row[it * 32 + lane];
        int c0 = v.x > 0.0f, c1 = v.y > 0.0f, c2 = v.z > 0.0f, c3 = v.w > 0.0f;
        int cnt = c0 + c1 + c2 + c3;
        int inc = cnt;
        #pragma unroll
        for (int o = 1; o < 32; o <<= 1) {
            int n = __shfl_up_sync(0xffffffffu, inc, o);
            if (lane >= o) inc += n;
        }
        int pos = base + inc - cnt;
        int j0 = (it * 32 + lane) * 4;
        if (c0) out[pos++] = j0;
        if (c1) out[pos++] = j0 + 1;
        if (c2) out[pos++] = j0 + 2;
        if (c3) out[pos++] = j0 + 3;
        base += __shfl_sync(0xffffffffu, inc, 31);
    }
    if (lane == 0) g_cnt[warp] = base;
}

__device__ __forceinline__ float lrelu(float x) { return x > 0.0f ? x : 0.2f * x; }

// ---------------- K3: fused masked softmax + aggregation -------------------
// Warp per (h,b,i). Pass 1 caches (uint4-offset, s_src[j]) per neighbor in
// smem (CAP entries; gmem fallback beyond). Pass 2: lane-parallel exp
// weights, 4 neighbors per LDG.128 iteration via lane-group broadcast.
__global__ void k_att(float* __restrict__ out) {
    __shared__ int   s_off[8][CAP];
    __shared__ float s_ssv[8][CAP];

    int gw = (blockIdx.x * blockDim.x + threadIdx.x) >> 5;
    int lane = threadIdx.x & 31;
    if (gw >= HBN) return;
    const int w = (threadIdx.x >> 5);

    const int h   = gw / BN;
    const int rem = gw - h * BN;          // b*N + i
    const int b   = rem / NN;

    const int    c   = g_cnt[rem];
    const int*   lst = g_nbr + (size_t)rem * NN;
    const float* ss  = g_ssrc + (size_t)h * BN + (size_t)b * NN;
    const float  sdi = g_sdst[gw];

    // pass 1: row max (lrelu monotone) + cache (off, ss) in smem
    float m = -1e30f;
    for (int t = lane; t < c; t += 32) {
        int j = lst[t];
        float sv = ss[j];
        m = fmaxf(m, sv);
        if (t < CAP) { s_off[w][t] = j * 8; s_ssv[w][t] = sv; }
    }
    #pragma unroll
    for (int o = 16; o; o >>= 1) m = fmaxf(m, __shfl_xor_sync(0xffffffffu, m, o));
    const float rowmax = lrelu(sdi + m);
    __syncwarp();

    // pass 2
    const uint4* base = (const uint4*)(g_hh + ((size_t)h * BN + (size_t)b * NN) * OO);
    const int g = lane >> 3;
    const int s = lane & 7;

    float2 a0 = {0,0}, a1 = {0,0}, a2 = {0,0}, a3 = {0,0};
    float Z = 0.0f;

    for (int t0 = 0; t0 < c; t0 += 32) {
        int   t = t0 + lane;
        float e = 0.0f;
        int   off = 0;
        if (t < c) {
            float sv;
            if (t < CAP) { off = s_off[w][t]; sv = s_ssv[w][t]; }
            else         { int j = lst[t]; off = j * 8; sv = ss[j]; }
            e = __expf(lrelu(sdi + sv) - rowmax);
        }
        Z += e;
        #pragma unroll
        for (int k = 0; k < 8; k++) {
            int   idx = k * 4 + g;
            float ek  = __shfl_sync(0xffffffffu, e,   idx);
            int   ofk = __shfl_sync(0xffffffffu, off, idx);
            uint4 raw = base[ofk + s];
            const __half2* ph = (const __half2*)&raw;
            float2 f0 = __half22float2(ph[0]);
            float2 f1 = __half22float2(ph[1]);
            float2 f2 = __half22float2(ph[2]);
            float2 f3 = __half22float2(ph[3]);
            a0.x = fmaf(ek, f0.x, a0.x); a0.y = fmaf(ek, f0.y, a0.y);
            a1.x = fmaf(ek, f1.x, a1.x); a1.y = fmaf(ek, f1.y, a1.y);
            a2.x = fmaf(ek, f2.x, a2.x); a2.y = fmaf(ek, f2.y, a2.y);
            a3.x = fmaf(ek, f3.x, a3.x); a3.y = fmaf(ek, f3.y, a3.y);
        }
    }

    // combine lane groups (xor 8, 16) and reduce Z (full butterfly)
    #pragma unroll
    for (int o = 8; o <= 16; o <<= 1) {
        a0.x += __shfl_xor_sync(0xffffffffu, a0.x, o);
        a0.y += __shfl_xor_sync(0xffffffffu, a0.y, o);
        a1.x += __shfl_xor_sync(0xffffffffu, a1.x, o);
        a1.y += __shfl_xor_sync(0xffffffffu, a1.y, o);
        a2.x += __shfl_xor_sync(0xffffffffu, a2.x, o);
        a2.y += __shfl_xor_sync(0xffffffffu, a2.y, o);
        a3.x += __shfl_xor_sync(0xffffffffu, a3.x, o);
        a3.y += __shfl_xor_sync(0xffffffffu, a3.y, o);
    }
    #pragma unroll
    for (int o = 16; o; o >>= 1) Z += __shfl_xor_sync(0xffffffffu, Z, o);

    if (lane < 8) {
        float inv = 1.0f / Z;
        float4 r0 = make_float4(fmaxf(a0.x*inv,0.f), fmaxf(a0.y*inv,0.f),
                                fmaxf(a1.x*inv,0.f), fmaxf(a1.y*inv,0.f));
        float4 r1 = make_float4(fmaxf(a2.x*inv,0.f), fmaxf(a2.y*inv,0.f),
                                fmaxf(a3.x*inv,0.f), fmaxf(a3.y*inv,0.f));
        float* op = out + (size_t)rem * (HH * OO) + h * OO + s * 8;
        ((float4*)op)[0] = r0;
        ((float4*)op)[1] = r1;
    }
}

// --------------------------------- launch ---------------------------------
extern "C" void kernel_launch(void* const* d_in, const int* in_sizes, int n_in,
                              void* d_out, int out_size) {
    const float* x     = (const float*)d_in[0];
    const float* adj   = (const float*)d_in[1];
    const float* W     = (const float*)d_in[2];
    const float* a_src = (const float*)d_in[3];
    const float* a_dst = (const float*)d_in[4];
    float* out = (float*)d_out;

    k_wa<<<(HH * FF * 32) / 256, 256>>>(W, a_src, a_dst);
    k_compact<<<(BN * 32) / 256, 256>>>(adj);
    k_scores<<<BN / 8, 256>>>(x);
    k_hgemm<<<dim3(BN / 64, HH), 128>>>(0);
    k_att<<<(HBN * 32) / 256, 256>>>(out);
}